// round 7
// baseline (speedup 1.0000x reference)
#include <cuda_runtime.h>
#include <cuda_bf16.h>
#include <math.h>
#include <stdint.h>

#define LSEQ 4096
#define DIM 512
#define NH 8
#define HS 64
#define CHUNK 128
#define NC 32            // LSEQ / CHUNK
#define PCOLS 2048       // q(512) | k(512) | v(512) | gate(512)
#define HALF 32          // HS/2
#define KSPLIT 1536      // 3 * DIM (bf16x3 folded into K)

typedef __nv_bfloat16 bf16;

// ---------------- scratch (device globals; no allocation allowed) ----------------
__device__ float d_proj[LSEQ * PCOLS];
__device__ float d_sinT[LSEQ * HALF];
__device__ float d_cosT[LSEQ * HALF];
__device__ float d_sclQ[LSEQ * HALF];
__device__ float d_sclK[LSEQ * HALF];
__device__ float d_Sloc[NH * NC * HS * HS];
__device__ float d_ret [NH * LSEQ * HS];
// bf16x3 packed operands for the big GEMMs
__device__ bf16 d_A2 [LSEQ * KSPLIT];
__device__ bf16 d_B2 [PCOLS * KSPLIT];
__device__ bf16 d_WO2[DIM * KSPLIT];
__device__ bf16 d_g2 [LSEQ * KSPLIT];
// retention-core folded operands
__device__ bf16 d_Q2[NH * LSEQ * 192];        // [n][c][t][192] = [qh|ql|qh]
__device__ bf16 d_K2[NH * LSEQ * 192];        // [kh|kh|kl]
__device__ bf16 d_V2[NH * NC * 64 * 384];     // [n][c][j][384] = v^T folded [vh|vh|vl]
__device__ bf16 d_S2[NH * NC * 64 * 192];     // [n][c][j][192] = S_in^T folded [Sh|Sh|Sl]
__device__ bf16 d_P2[NH * NC * CHUNK * 384];  // [n][c][t][384] = [Ph|Pl|Ph]

__device__ __forceinline__ float gamma_of(int n) {
    double lo = log(1.0 / 32.0), hi = log(1.0 / 512.0);
    return (float)(1.0 - exp(lo + (hi - lo) * ((double)n / 7.0)));
}

__device__ __forceinline__ uint32_t smem_u32(const void* p) {
    uint32_t a;
    asm("{ .reg .u64 t; cvta.to.shared.u64 t, %1; cvt.u32.u64 %0, t; }" : "=r"(a) : "l"(p));
    return a;
}
#define CP_ASYNC16(s, g) \
    asm volatile("cp.async.cg.shared.global [%0], [%1], 16;" :: "r"(s), "l"(g))
#define CP_COMMIT() asm volatile("cp.async.commit_group;" ::: "memory")
#define CP_WAIT0()  asm volatile("cp.async.wait_group 0;" ::: "memory")
#define CP_WAIT1()  asm volatile("cp.async.wait_group 1;" ::: "memory")

#define MMA16816(acc, a, b) \
    asm volatile( \
        "mma.sync.aligned.m16n8k16.row.col.f32.bf16.bf16.f32 " \
        "{%0,%1,%2,%3}, {%4,%5,%6,%7}, {%8,%9}, {%0,%1,%2,%3};" \
        : "+f"((acc)[0]), "+f"((acc)[1]), "+f"((acc)[2]), "+f"((acc)[3]) \
        : "r"((a)[0]), "r"((a)[1]), "r"((a)[2]), "r"((a)[3]), \
          "r"((b)[0]), "r"((b)[1]))

// ---------------- xPos tables (double precision for exactness) ----------------
__global__ void k_tables() {
    int idx = blockIdx.x * blockDim.x + threadIdx.x;
    if (idx >= LSEQ * HALF) return;
    int l = idx >> 5, j = idx & 31;
    double sv   = (2.0 * j + 0.4 * 64.0) / (1.4 * 64.0);
    double sc   = pow(sv, (double)l / 512.0);
    double invf = pow(10000.0, -((double)j) / 32.0);
    double ang  = (double)l * invf;
    d_sinT[idx] = (float)sin(ang);
    d_cosT[idx] = (float)cos(ang);
    d_sclQ[idx] = (float)sc;
    d_sclK[idx] = (float)(1.0 / sc);
}

// ---------------- X -> A2 = [hi | lo | hi] ----------------
__global__ void k_convA(const float* __restrict__ X) {
    int idx = blockIdx.x * blockDim.x + threadIdx.x;
    if (idx >= LSEQ * DIM) return;
    int l = idx >> 9, k = idx & 511;
    float x = X[idx];
    bf16 h = __float2bfloat16(x);
    bf16 lo = __float2bfloat16(x - __bfloat162float(h));
    size_t b = (size_t)l * KSPLIT;
    d_A2[b + k] = h; d_A2[b + 512 + k] = lo; d_A2[b + 1024 + k] = h;
}

// ---------------- pack W_Q|W_K|W_V|W_G transposed -> B2 [2048][1536] = [hi | hi | lo] ----------------
__global__ void k_packB(const float* __restrict__ WQ, const float* __restrict__ WK,
                        const float* __restrict__ WV, const float* __restrict__ WG) {
    int idx = blockIdx.x * blockDim.x + threadIdx.x;
    if (idx >= PCOLS * DIM) return;
    int n = idx / DIM, k = idx % DIM;
    float v;
    if (n < 512)       { int nh = n >> 6, h = n & 63;            v = WQ[(nh * DIM + k) * HS + h]; }
    else if (n < 1024) { int c = n - 512,  nh = c >> 6, h = c & 63; v = WK[(nh * DIM + k) * HS + h]; }
    else if (n < 1536) { int c = n - 1024, nh = c >> 6, h = c & 63; v = WV[(nh * DIM + k) * HS + h]; }
    else v = WG[k * 512 + (n - 1536)];
    bf16 h2 = __float2bfloat16(v);
    bf16 lo = __float2bfloat16(v - __bfloat162float(h2));
    size_t b = (size_t)n * KSPLIT;
    d_B2[b + k] = h2; d_B2[b + 512 + k] = h2; d_B2[b + 1024 + k] = lo;
}

// ---------------- W_O^T -> WO2 [512][1536] = [hi | hi | lo] ----------------
__global__ void k_packWO(const float* __restrict__ WO) {
    int idx = blockIdx.x * blockDim.x + threadIdx.x;
    if (idx >= DIM * DIM) return;
    int n = idx / DIM, k = idx % DIM;
    float v = WO[k * DIM + n];
    bf16 h = __float2bfloat16(v);
    bf16 lo = __float2bfloat16(v - __bfloat162float(h));
    size_t b = (size_t)n * KSPLIT;
    d_WO2[b + k] = h; d_WO2[b + 512 + k] = h; d_WO2[b + 1024 + k] = lo;
}

// ---------------- bf16 HMMA GEMM, 3-stage cp.async pipeline ----------------
// C[M,N] = A[M,K] @ B[N,K]^T, K=1536. BM=128 BN=128 BK=32, 256 threads.
// dyn smem: 3 stages x (A 128x40 + B 128x40) bf16 = 61440 bytes.
#define MSTAGE 3
#define STG_ELEMS (2 * 128 * 40)
__global__ void __launch_bounds__(256) k_mma(const bf16* __restrict__ A,
                                             const bf16* __restrict__ B,
                                             float* __restrict__ C, int N) {
    extern __shared__ bf16 sm[];
    const int Ktot = KSPLIT, KT = KSPLIT / 32;

    int tid = threadIdx.x, lane = tid & 31, wid = tid >> 5;
    int wm = wid & 1, wn = wid >> 1;
    int m0 = blockIdx.y * 128, n0 = blockIdx.x * 128;

    float acc[4][4][4];
#pragma unroll
    for (int i = 0; i < 4; i++)
#pragma unroll
        for (int j = 0; j < 4; j++)
#pragma unroll
            for (int r2 = 0; r2 < 4; r2++) acc[i][j][r2] = 0.f;

    int lrow = tid >> 2, lc16 = tid & 3;
    auto load_AB = [&](int buf, int k0) {
        bf16* Ad = sm + buf * STG_ELEMS;
        bf16* Bd = Ad + 128 * 40;
#pragma unroll
        for (int i = 0; i < 2; i++) {
            int row = lrow + i * 64;
            CP_ASYNC16(smem_u32(Ad + row * 40 + lc16 * 8),
                       A + (size_t)(m0 + row) * Ktot + k0 + lc16 * 8);
            CP_ASYNC16(smem_u32(Bd + row * 40 + lc16 * 8),
                       B + (size_t)(n0 + row) * Ktot + k0 + lc16 * 8);
        }
    };

    // prologue: stages 0..MSTAGE-2
#pragma unroll
    for (int s = 0; s < MSTAGE - 1; s++) { load_AB(s, s * 32); CP_COMMIT(); }

    for (int kt = 0; kt < KT; kt++) {
        asm volatile("cp.async.wait_group %0;" :: "n"(MSTAGE - 2) : "memory");
        __syncthreads();
        int nld = kt + MSTAGE - 1;
        if (nld < KT) load_AB(nld % MSTAGE, nld * 32);
        CP_COMMIT();

        bf16* Asp = sm + (kt % MSTAGE) * STG_ELEMS;
        bf16* Bsp = Asp + 128 * 40;
#pragma unroll
        for (int ks = 0; ks < 2; ks++) {
            int k0 = ks * 16;
            uint32_t af[4][4];
#pragma unroll
            for (int mi = 0; mi < 4; mi++) {
                uint32_t addr = smem_u32(Asp + (wm * 64 + mi * 16 + (lane & 15)) * 40
                                             + k0 + (lane >> 4) * 8);
                asm volatile("ldmatrix.sync.aligned.m8n8.x4.shared.b16 {%0,%1,%2,%3}, [%4];"
                    : "=r"(af[mi][0]), "=r"(af[mi][1]), "=r"(af[mi][2]), "=r"(af[mi][3])
                    : "r"(addr));
            }
            uint32_t bfr[4][2];
#pragma unroll
            for (int ni = 0; ni < 4; ni++) {
                int l16 = lane & 15;
                uint32_t addr = smem_u32(Bsp + (wn * 32 + ni * 8 + (l16 & 7)) * 40
                                             + k0 + (l16 >> 3) * 8);
                asm volatile("ldmatrix.sync.aligned.m8n8.x2.shared.b16 {%0,%1}, [%2];"
                    : "=r"(bfr[ni][0]), "=r"(bfr[ni][1]) : "r"(addr));
            }
#pragma unroll
            for (int mi = 0; mi < 4; mi++)
#pragma unroll
                for (int ni = 0; ni < 4; ni++)
                    MMA16816(acc[mi][ni], af[mi], bfr[ni]);
        }
    }

#pragma unroll
    for (int mi = 0; mi < 4; mi++)
#pragma unroll
        for (int ni = 0; ni < 4; ni++) {
            int row = m0 + wm * 64 + mi * 16 + (lane >> 2);
            int col = n0 + wn * 32 + ni * 8 + (lane & 3) * 2;
            float2 v0 = {acc[mi][ni][0], acc[mi][ni][1]};
            float2 v1 = {acc[mi][ni][2], acc[mi][ni][3]};
            *(float2*)&C[(size_t)row * N + col]       = v0;
            *(float2*)&C[(size_t)(row + 8) * N + col] = v1;
        }
}

// ---------------- epilogue: xPos rotate -> Q2/K2 folded; k f32 back; v -> V2; silu gate ----------------
__global__ void k_epi() {
    int idx = blockIdx.x * blockDim.x + threadIdx.x;
    if (idx >= LSEQ * 1024) return;
    int l = idx >> 10, u = idx & 1023;
    int cch = l >> 7, t = l & 127;
    if (u < 512) {
        bool isK = (u >= 256);
        int p = u & 255;
        int n = p >> 5, j5 = p & 31;
        size_t pb = (size_t)l * PCOLS + (isK ? 512 : 0) + n * 64 + 2 * j5;
        float x1 = d_proj[pb], x2 = d_proj[pb + 1];
        float sc = isK ? d_sclK[l * 32 + j5] : d_sclQ[l * 32 + j5];
        float si = d_sinT[l * 32 + j5] * sc;
        float co = d_cosT[l * 32 + j5] * sc;
        float r1 = x1 * co - x2 * si;
        float r2 = x2 * co + x1 * si;
        bf16 h1 = __float2bfloat16(r1), h2 = __float2bfloat16(r2);
        bf16 l1 = __float2bfloat16(r1 - __bfloat162float(h1));
        bf16 l2 = __float2bfloat16(r2 - __bfloat162float(h2));
        size_t qb = ((size_t)(n * NC + cch) * 128 + t) * 192 + 2 * j5;
        if (!isK) {
            d_Q2[qb] = h1;       d_Q2[qb + 1] = h2;
            d_Q2[qb + 64] = l1;  d_Q2[qb + 65] = l2;
            d_Q2[qb + 128] = h1; d_Q2[qb + 129] = h2;
        } else {
            d_proj[pb] = r1; d_proj[pb + 1] = r2;   // f32 k for locstate
            d_K2[qb] = h1;       d_K2[qb + 1] = h2;
            d_K2[qb + 64] = h1;  d_K2[qb + 65] = h2;
            d_K2[qb + 128] = l1; d_K2[qb + 129] = l2;
        }
    } else {
        int vd = u - 512;
        int n = vd >> 6, j = vd & 63;
        float xv = d_proj[(size_t)l * PCOLS + 1024 + vd];
        bf16 vh = __float2bfloat16(xv);
        bf16 vl = __float2bfloat16(xv - __bfloat162float(vh));
        size_t vb = ((size_t)(n * NC + cch) * 64 + j) * 384 + t;  // V^T folded
        d_V2[vb] = vh; d_V2[vb + 128] = vh; d_V2[vb + 256] = vl;
        size_t gb = (size_t)l * PCOLS + 1536 + vd;
        float x = d_proj[gb];
        d_proj[gb] = x / (1.f + expf(-x));
    }
}

// ---------------- per-chunk local decay state (SIMT fp32) ----------------
__global__ void k_locstate() {
    int c = blockIdx.x, n = blockIdx.y;
    float g = gamma_of(n);
    __shared__ float sk[64][64];
    __shared__ float sv[64][64];
    __shared__ float wgt[CHUNK];
    int tid = threadIdx.x;
    if (tid < CHUNK) wgt[tid] = (float)pow((double)g, (double)(CHUNK - 1 - tid));
    __syncthreads();
    int tx = tid & 15, ty = tid >> 4;
    float acc[4][4];
#pragma unroll
    for (int i = 0; i < 4; i++)
#pragma unroll
        for (int j = 0; j < 4; j++) acc[i][j] = 0.f;

    for (int half = 0; half < 2; half++) {
#pragma unroll
        for (int i = 0; i < 16; i++) {
            int t4 = tid + i * 256;
            int rr = t4 >> 6, cc = t4 & 63;
            int s = c * CHUNK + half * 64 + rr;
            sk[rr][cc] = d_proj[(size_t)s * PCOLS + 512  + n * 64 + cc] * wgt[half * 64 + rr];
            sv[rr][cc] = d_proj[(size_t)s * PCOLS + 1024 + n * 64 + cc];
        }
        __syncthreads();
#pragma unroll
        for (int t = 0; t < 64; t++) {
            float4 a4 = *(const float4*)&sk[t][ty * 4];
            float4 b4 = *(const float4*)&sv[t][tx * 4];
            float a[4] = {a4.x, a4.y, a4.z, a4.w};
            float b[4] = {b4.x, b4.y, b4.z, b4.w};
#pragma unroll
            for (int i = 0; i < 4; i++)
#pragma unroll
                for (int j = 0; j < 4; j++) acc[i][j] += a[i] * b[j];
        }
        __syncthreads();
    }
#pragma unroll
    for (int i = 0; i < 4; i++)
#pragma unroll
        for (int j = 0; j < 4; j++)
            d_Sloc[(size_t)((n * NC + c) * 64 + ty * 4 + i) * 64 + tx * 4 + j] = acc[i][j];
}

// ---------------- parallel scan -> S2 folded ----------------
__global__ void k_scan2() {
    int idx = blockIdx.x * blockDim.x + threadIdx.x;   // 32768
    int n = idx >> 12, e = idx & 4095;
    int i = e >> 6, j = e & 63;
    float g = gamma_of(n);
    float g128 = (float)pow((double)g, 128.0);
    float s = 0.f;
#pragma unroll 1
    for (int c = 0; c < NC; c++) {
        bf16 sh = __float2bfloat16(s);
        bf16 sl = __float2bfloat16(s - __bfloat162float(sh));
        size_t sb = ((size_t)(n * NC + c) * 64 + j) * 192 + i;
        d_S2[sb] = sh; d_S2[sb + 64] = sh; d_S2[sb + 128] = sl;
        s = g128 * s + d_Sloc[(size_t)(n * NC + c) * 4096 + e];
    }
}

// ---------------- phase A: P = (Q K^T) ⊙ decay, per (n,c), HMMA, emit folded P2 ----------------
__global__ void __launch_bounds__(256) k_pa() {
    __shared__ bf16 As[2][128][40];
    __shared__ bf16 Bs[2][128][40];
    __shared__ float gpow[CHUNK];
    int c = blockIdx.x, n = blockIdx.y;
    int tid = threadIdx.x, lane = tid & 31, wid = tid >> 5;
    int wm = wid & 1, wn = wid >> 1;
    float g = gamma_of(n);
    if (tid < CHUNK) gpow[tid] = (float)pow((double)g, (double)tid);

    const bf16* A = d_Q2 + (size_t)(n * NC + c) * 128 * 192;
    const bf16* B = d_K2 + (size_t)(n * NC + c) * 128 * 192;

    float acc[4][4][4];
#pragma unroll
    for (int i = 0; i < 4; i++)
#pragma unroll
        for (int j = 0; j < 4; j++)
#pragma unroll
            for (int r2 = 0; r2 < 4; r2++) acc[i][j][r2] = 0.f;

    auto load_AB = [&](int buf, int k0) {
#pragma unroll
        for (int i = 0; i < 2; i++) {
            int ch = tid + i * 256;
            int row = ch >> 2, c16 = ch & 3;
            CP_ASYNC16(smem_u32(&As[buf][row][c16 * 8]), A + (size_t)row * 192 + k0 + c16 * 8);
            CP_ASYNC16(smem_u32(&Bs[buf][row][c16 * 8]), B + (size_t)row * 192 + k0 + c16 * 8);
        }
    };

    const int KT = 6;
    load_AB(0, 0);
    CP_COMMIT();
    int cur = 0;
    for (int kt = 0; kt < KT; kt++) {
        if (kt + 1 < KT) { load_AB(cur ^ 1, (kt + 1) * 32); CP_COMMIT(); CP_WAIT1(); }
        else CP_WAIT0();
        __syncthreads();
#pragma unroll
        for (int ks = 0; ks < 2; ks++) {
            int k0 = ks * 16;
            uint32_t af[4][4];
#pragma unroll
            for (int mi = 0; mi < 4; mi++) {
                uint32_t addr = smem_u32(&As[cur][wm * 64 + mi * 16 + (lane & 15)]
                                            [k0 + (lane >> 4) * 8]);
                asm volatile("ldmatrix.sync.aligned.m8n8.x4.shared.b16 {%0,%1,%2,%3}, [%4];"
                    : "=r"(af[mi][0]), "=r"(af[mi][1]), "=r"(af[mi][2]), "=r"(af[mi][3])
                    : "r"(addr));
            }
            uint32_t bfr[4][2];
#pragma unroll
            for (int ni = 0; ni < 4; ni++) {
                int l16 = lane & 15;
                uint32_t addr = smem_u32(&Bs[cur][wn * 32 + ni * 8 + (l16 & 7)]
                                            [k0 + (l16 >> 3) * 8]);
                asm volatile("ldmatrix.sync.aligned.m8n8.x2.shared.b16 {%0,%1}, [%2];"
                    : "=r"(bfr[ni][0]), "=r"(bfr[ni][1]) : "r"(addr));
            }
#pragma unroll
            for (int mi = 0; mi < 4; mi++)
#pragma unroll
                for (int ni = 0; ni < 4; ni++)
                    MMA16816(acc[mi][ni], af[mi], bfr[ni]);
        }
        __syncthreads();
        cur ^= 1;
    }

    size_t pbase = (size_t)(n * NC + c) * 128 * 384;
#pragma unroll
    for (int mi = 0; mi < 4; mi++)
#pragma unroll
        for (int ni = 0; ni < 4; ni++) {
            int s0 = wn * 32 + ni * 8 + (lane & 3) * 2;
#pragma unroll
            for (int h = 0; h < 2; h++) {
                int t = wm * 64 + mi * 16 + (lane >> 2) + h * 8;
                float p0 = acc[mi][ni][h * 2], p1 = acc[mi][ni][h * 2 + 1];
                p0 = (s0 <= t)     ? p0 * gpow[t - s0]     : 0.f;
                p1 = (s0 + 1 <= t) ? p1 * gpow[t - s0 - 1] : 0.f;
                bf16 h0 = __float2bfloat16(p0), h1b = __float2bfloat16(p1);
                __nv_bfloat162 hh; hh.x = h0; hh.y = h1b;
                __nv_bfloat162 ll;
                ll.x = __float2bfloat16(p0 - __bfloat162float(h0));
                ll.y = __float2bfloat16(p1 - __bfloat162float(h1b));
                size_t base = pbase + (size_t)t * 384 + s0;
                *(__nv_bfloat162*)&d_P2[base]       = hh;
                *(__nv_bfloat162*)&d_P2[base + 128] = ll;
                *(__nv_bfloat162*)&d_P2[base + 256] = hh;
            }
        }
}

// ---------------- phase B: out = P@V + g^(t+1) * Q@S_in, per (n,c), HMMA ----------------
__global__ void __launch_bounds__(256) k_pb() {
    __shared__ bf16 As[2][128][40];
    __shared__ bf16 Bs[2][64][40];
    __shared__ float gpow[CHUNK + 1];
    int c = blockIdx.x, n = blockIdx.y;
    int tid = threadIdx.x, lane = tid & 31, wid = tid >> 5;
    int wm = wid & 3, wn = wid >> 2;
    float g = gamma_of(n);
    if (tid <= CHUNK) gpow[tid] = (float)pow((double)g, (double)tid);

    float acc1[2][4][4], acc2[2][4][4];
#pragma unroll
    for (int i = 0; i < 2; i++)
#pragma unroll
        for (int j = 0; j < 4; j++)
#pragma unroll
            for (int r2 = 0; r2 < 4; r2++) { acc1[i][j][r2] = 0.f; acc2[i][j][r2] = 0.f; }

    auto run_pass = [&](const bf16* A, const bf16* B, int Ktot, float (*acc)[4][4]) {
        auto load_AB = [&](int buf, int k0) {
#pragma unroll
            for (int i = 0; i < 2; i++) {
                int ch = tid + i * 256;
                int row = ch >> 2, c16 = ch & 3;
                CP_ASYNC16(smem_u32(&As[buf][row][c16 * 8]), A + (size_t)row * Ktot + k0 + c16 * 8);
            }
            int row = tid >> 2, c16 = tid & 3;
            CP_ASYNC16(smem_u32(&Bs[buf][row][c16 * 8]), B + (size_t)row * Ktot + k0 + c16 * 8);
        };
        int KT = Ktot / 32;
        load_AB(0, 0);
        CP_COMMIT();
        int cur = 0;
        for (int kt = 0; kt < KT; kt++) {
            if (kt + 1 < KT) { load_AB(cur ^ 1, (kt + 1) * 32); CP_COMMIT(); CP_WAIT1(); }
            else CP_WAIT0();
            __syncthreads();
#pragma unroll
            for (int ks = 0; ks < 2; ks++) {
                int k0 = ks * 16;
                uint32_t af[2][4];
#pragma unroll
                for (int mi = 0; mi < 2; mi++) {
                    uint32_t addr = smem_u32(&As[cur][wm * 32 + mi * 16 + (lane & 15)]
                                                [k0 + (lane >> 4) * 8]);
                    asm volatile("ldmatrix.sync.aligned.m8n8.x4.shared.b16 {%0,%1,%2,%3}, [%4];"
                        : "=r"(af[mi][0]), "=r"(af[mi][1]), "=r"(af[mi][2]), "=r"(af[mi][3])
                        : "r"(addr));
                }
                uint32_t bfr[4][2];
#pragma unroll
                for (int ni = 0; ni < 4; ni++) {
                    int l16 = lane & 15;
                    uint32_t addr = smem_u32(&Bs[cur][wn * 32 + ni * 8 + (l16 & 7)]
                                                [k0 + (l16 >> 3) * 8]);
                    asm volatile("ldmatrix.sync.aligned.m8n8.x2.shared.b16 {%0,%1}, [%2];"
                        : "=r"(bfr[ni][0]), "=r"(bfr[ni][1]) : "r"(addr));
                }
#pragma unroll
                for (int mi = 0; mi < 2; mi++)
#pragma unroll
                    for (int ni = 0; ni < 4; ni++)
                        MMA16816(acc[mi][ni], af[mi], bfr[ni]);
            }
            __syncthreads();
            cur ^= 1;
        }
    };

    run_pass(d_P2 + (size_t)(n * NC + c) * 128 * 384,
             d_V2 + (size_t)(n * NC + c) * 64 * 384, 384, acc1);
    run_pass(d_Q2 + (size_t)(n * NC + c) * 128 * 192,
             d_S2 + (size_t)(n * NC + c) * 64 * 192, 192, acc2);

#pragma unroll
    for (int mi = 0; mi < 2; mi++)
#pragma unroll
        for (int ni = 0; ni < 4; ni++) {
            int j = wn * 32 + ni * 8 + (lane & 3) * 2;
#pragma unroll
            for (int h = 0; h < 2; h++) {
                int t = wm * 32 + mi * 16 + (lane >> 2) + h * 8;
                float dec = gpow[t + 1];
                float2 o;
                o.x = acc1[mi][ni][h * 2]     + dec * acc2[mi][ni][h * 2];
                o.y = acc1[mi][ni][h * 2 + 1] + dec * acc2[mi][ni][h * 2 + 1];
                *(float2*)&d_ret[(size_t)(n * LSEQ + c * CHUNK + t) * 64 + j] = o;
            }
        }
}

// ---------------- groupnorm * gate -> bf16x3 packed rows of d_g2 ----------------
__global__ void k_gnorm(const float* __restrict__ gnw, const float* __restrict__ gnb) {
    int warp = threadIdx.x >> 5, lane = threadIdx.x & 31;
    int grp = blockIdx.x * 8 + warp;
    int l = grp >> 3, n = grp & 7;
    const float* rp = &d_ret[(size_t)(n * LSEQ + l) * 64];
    float v0 = rp[lane], v1 = rp[lane + 32];
    float s = v0 + v1, ss = v0 * v0 + v1 * v1;
#pragma unroll
    for (int off = 16; off; off >>= 1) {
        s  += __shfl_xor_sync(0xffffffffu, s,  off);
        ss += __shfl_xor_sync(0xffffffffu, ss, off);
    }
    float mean = s * (1.f / 64.f);
    float var  = ss * (1.f / 64.f) - mean * mean;
    float inv  = rsqrtf(var + 1e-5f);
    int col = n * 64 + lane;
    float g0 = (v0 - mean) * inv * gnw[col]      + gnb[col];
    float g1 = (v1 - mean) * inv * gnw[col + 32] + gnb[col + 32];
    float gate0 = d_proj[(size_t)l * PCOLS + 1536 + col];
    float gate1 = d_proj[(size_t)l * PCOLS + 1536 + col + 32];
    float o0 = gate0 * g0, o1 = gate1 * g1;
    size_t b = (size_t)l * KSPLIT;
    bf16 h0 = __float2bfloat16(o0);
    bf16 h1 = __float2bfloat16(o1);
    d_g2[b + col]             = h0;
    d_g2[b + 512 + col]       = __float2bfloat16(o0 - __bfloat162float(h0));
    d_g2[b + 1024 + col]      = h0;
    d_g2[b + col + 32]        = h1;
    d_g2[b + 512 + col + 32]  = __float2bfloat16(o1 - __bfloat162float(h1));
    d_g2[b + 1024 + col + 32] = h1;
}

// ---------------- launch ----------------
extern "C" void kernel_launch(void* const* d_in, const int* in_sizes, int n_in,
                              void* d_out, int out_size) {
    (void)in_sizes; (void)n_in; (void)out_size;
    const float* X   = (const float*)d_in[0];
    const float* WQ  = (const float*)d_in[1];
    const float* WK  = (const float*)d_in[2];
    const float* WV  = (const float*)d_in[3];
    const float* WG  = (const float*)d_in[4];
    const float* WO  = (const float*)d_in[5];
    const float* gnw = (const float*)d_in[6];
    const float* gnb = (const float*)d_in[7];
    float* out = (float*)d_out;

    const int MMA_SMEM = MSTAGE * STG_ELEMS * 2;   // 61440 bytes
    cudaFuncSetAttribute(k_mma, cudaFuncAttributeMaxDynamicSharedMemorySize, MMA_SMEM);

    void *pProj = nullptr, *pA2 = nullptr, *pB2 = nullptr, *pWO2 = nullptr, *pG2 = nullptr;
    cudaGetSymbolAddress(&pProj, d_proj);
    cudaGetSymbolAddress(&pA2,  d_A2);
    cudaGetSymbolAddress(&pB2,  d_B2);
    cudaGetSymbolAddress(&pWO2, d_WO2);
    cudaGetSymbolAddress(&pG2,  d_g2);

    k_tables<<<(LSEQ * HALF + 255) / 256, 256>>>();
    k_convA<<<(LSEQ * DIM + 255) / 256, 256>>>(X);
    k_packB<<<(PCOLS * DIM + 255) / 256, 256>>>(WQ, WK, WV, WG);
    k_packWO<<<(DIM * DIM + 255) / 256, 256>>>(WO);
    k_mma<<<dim3(PCOLS / 128, LSEQ / 128), 256, MMA_SMEM>>>(
        (const bf16*)pA2, (const bf16*)pB2, (float*)pProj, PCOLS);
    k_epi<<<(LSEQ * 1024 + 255) / 256, 256>>>();
    k_locstate<<<dim3(NC, NH), 256>>>();
    k_scan2<<<128, 256>>>();
    k_pa<<<dim3(NC, NH), 256>>>();
    k_pb<<<dim3(NC, NH), 256>>>();
    k_gnorm<<<LSEQ, 256>>>(gnw, gnb);
    k_mma<<<dim3(DIM / 128, LSEQ / 128), 256, MMA_SMEM>>>(
        (const bf16*)pG2, (const bf16*)pWO2, out, DIM);
}

// round 11
// speedup vs baseline: 1.1331x; 1.1331x over previous
#include <cuda_runtime.h>
#include <cuda_bf16.h>
#include <cuda_fp16.h>
#include <math.h>
#include <stdint.h>

#define LSEQ 4096
#define DIM 512
#define NH 8
#define HS 64
#define CHUNK 128
#define NC 32            // LSEQ / CHUNK
#define PCOLS 2048       // q(512) | k(512) | v(512) | gate(512)
#define HALF 32          // HS/2
#define KG 1024          // 2 * DIM (fp16 one-sided split folded into K)

typedef __nv_bfloat16 bf16;
typedef __half fp16;

// ---------------- scratch (device globals; no allocation allowed) ----------------
__device__ float d_proj[LSEQ * PCOLS];
__device__ float d_sinT[LSEQ * HALF];
__device__ float d_cosT[LSEQ * HALF];
__device__ float d_sclQ[LSEQ * HALF];
__device__ float d_sclK[LSEQ * HALF];
__device__ float d_Sloc[NH * NC * HS * HS];
__device__ float d_ret [NH * LSEQ * HS];
// fp16 one-sided-split operands for the big GEMMs (K=1024)
__device__ fp16 d_A2 [LSEQ * KG];             // [Ah | Al]
__device__ fp16 d_B2 [PCOLS * KG];            // [Bh | Bh]
__device__ fp16 d_WO2[DIM * KG];              // [WOh | WOh]
__device__ fp16 d_g2 [LSEQ * KG];             // [gh | gl]
// retention-core folded operands (bf16x3, unchanged)
__device__ bf16 d_Q2[NH * LSEQ * 192];        // [n][c][t][192] = [qh|ql|qh]
__device__ bf16 d_K2[NH * LSEQ * 192];        // [kh|kh|kl]
__device__ bf16 d_V2[NH * NC * 64 * 384];     // [n][c][j][384] = v^T folded [vh|vh|vl]
__device__ bf16 d_S2[NH * NC * 64 * 192];     // [n][c][j][192] = S_in^T folded [Sh|Sh|Sl]
__device__ bf16 d_P2[NH * NC * CHUNK * 384];  // [n][c][t][384] = [Ph|Pl|Ph]

__device__ __forceinline__ float gamma_of(int n) {
    double lo = log(1.0 / 32.0), hi = log(1.0 / 512.0);
    return (float)(1.0 - exp(lo + (hi - lo) * ((double)n / 7.0)));
}

__device__ __forceinline__ uint32_t smem_u32(const void* p) {
    uint32_t a;
    asm("{ .reg .u64 t; cvta.to.shared.u64 t, %1; cvt.u32.u64 %0, t; }" : "=r"(a) : "l"(p));
    return a;
}
#define CP_ASYNC16(s, g) \
    asm volatile("cp.async.cg.shared.global [%0], [%1], 16;" :: "r"(s), "l"(g))
#define CP_COMMIT() asm volatile("cp.async.commit_group;" ::: "memory")
#define CP_WAIT0()  asm volatile("cp.async.wait_group 0;" ::: "memory")
#define CP_WAIT1()  asm volatile("cp.async.wait_group 1;" ::: "memory")

#define MMA16816(acc, a, b) \
    asm volatile( \
        "mma.sync.aligned.m16n8k16.row.col.f32.bf16.bf16.f32 " \
        "{%0,%1,%2,%3}, {%4,%5,%6,%7}, {%8,%9}, {%0,%1,%2,%3};" \
        : "+f"((acc)[0]), "+f"((acc)[1]), "+f"((acc)[2]), "+f"((acc)[3]) \
        : "r"((a)[0]), "r"((a)[1]), "r"((a)[2]), "r"((a)[3]), \
          "r"((b)[0]), "r"((b)[1]))

#define MMA16816H(acc, a, b) \
    asm volatile( \
        "mma.sync.aligned.m16n8k16.row.col.f32.f16.f16.f32 " \
        "{%0,%1,%2,%3}, {%4,%5,%6,%7}, {%8,%9}, {%0,%1,%2,%3};" \
        : "+f"((acc)[0]), "+f"((acc)[1]), "+f"((acc)[2]), "+f"((acc)[3]) \
        : "r"((a)[0]), "r"((a)[1]), "r"((a)[2]), "r"((a)[3]), \
          "r"((b)[0]), "r"((b)[1]))

// ---------------- xPos tables (double precision for exactness) ----------------
__global__ void k_tables() {
    int idx = blockIdx.x * blockDim.x + threadIdx.x;
    if (idx >= LSEQ * HALF) return;
    int l = idx >> 5, j = idx & 31;
    double sv   = (2.0 * j + 0.4 * 64.0) / (1.4 * 64.0);
    double sc   = pow(sv, (double)l / 512.0);
    double invf = pow(10000.0, -((double)j) / 32.0);
    double ang  = (double)l * invf;
    d_sinT[idx] = (float)sin(ang);
    d_cosT[idx] = (float)cos(ang);
    d_sclQ[idx] = (float)sc;
    d_sclK[idx] = (float)(1.0 / sc);
}

// ---------------- X -> A2 = [Ah | Al] fp16 ----------------
__global__ void k_convA(const float* __restrict__ X) {
    int idx = blockIdx.x * blockDim.x + threadIdx.x;
    if (idx >= LSEQ * DIM) return;
    int l = idx >> 9, k = idx & 511;
    float x = X[idx];
    fp16 h = __float2half(x);
    fp16 lo = __float2half(x - __half2float(h));
    size_t b = (size_t)l * KG;
    d_A2[b + k] = h; d_A2[b + 512 + k] = lo;
}

// ---------------- pack W_Q|W_K|W_V|W_G transposed -> B2 [2048][1024] = [Bh | Bh] ----------------
__global__ void k_packB(const float* __restrict__ WQ, const float* __restrict__ WK,
                        const float* __restrict__ WV, const float* __restrict__ WG) {
    int idx = blockIdx.x * blockDim.x + threadIdx.x;
    if (idx >= PCOLS * DIM) return;
    int n = idx / DIM, k = idx % DIM;
    float v;
    if (n < 512)       { int nh = n >> 6, h = n & 63;            v = WQ[(nh * DIM + k) * HS + h]; }
    else if (n < 1024) { int c = n - 512,  nh = c >> 6, h = c & 63; v = WK[(nh * DIM + k) * HS + h]; }
    else if (n < 1536) { int c = n - 1024, nh = c >> 6, h = c & 63; v = WV[(nh * DIM + k) * HS + h]; }
    else v = WG[k * 512 + (n - 1536)];
    fp16 h2 = __float2half(v);
    size_t b = (size_t)n * KG;
    d_B2[b + k] = h2; d_B2[b + 512 + k] = h2;
}

// ---------------- W_O^T -> WO2 [512][1024] = [WOh | WOh] ----------------
__global__ void k_packWO(const float* __restrict__ WO) {
    int idx = blockIdx.x * blockDim.x + threadIdx.x;
    if (idx >= DIM * DIM) return;
    int n = idx / DIM, k = idx % DIM;
    float v = WO[k * DIM + n];
    fp16 h = __float2half(v);
    size_t b = (size_t)n * KG;
    d_WO2[b + k] = h; d_WO2[b + 512 + k] = h;
}

// ---------------- fp16 HMMA GEMM (R4-proven 2-stage): C[M,N] = A[M,K] @ B[N,K]^T, K=1024 ----------------
// BM=128 BN=128 BK=32, 256 threads (8 warps 2x4), warp tile 64x32 via m16n8k16.
__global__ void __launch_bounds__(256) k_mma(const fp16* __restrict__ A,
                                             const fp16* __restrict__ B,
                                             float* __restrict__ C, int N) {
    __shared__ fp16 As[2][128][40];
    __shared__ fp16 Bs[2][128][40];
    const int Ktot = KG, KT = KG / 32;

    int tid = threadIdx.x, lane = tid & 31, wid = tid >> 5;
    int wm = wid & 1, wn = wid >> 1;
    int m0 = blockIdx.y * 128, n0 = blockIdx.x * 128;

    float acc[4][4][4];
#pragma unroll
    for (int i = 0; i < 4; i++)
#pragma unroll
        for (int j = 0; j < 4; j++)
#pragma unroll
            for (int r2 = 0; r2 < 4; r2++) acc[i][j][r2] = 0.f;

    auto load_AB = [&](int buf, int k0) {
#pragma unroll
        for (int i = 0; i < 2; i++) {
            int ch = tid + i * 256;
            int row = ch >> 2, c16 = ch & 3;
            CP_ASYNC16(smem_u32(&As[buf][row][c16 * 8]),
                       A + (size_t)(m0 + row) * Ktot + k0 + c16 * 8);
            CP_ASYNC16(smem_u32(&Bs[buf][row][c16 * 8]),
                       B + (size_t)(n0 + row) * Ktot + k0 + c16 * 8);
        }
    };

    load_AB(0, 0);
    CP_COMMIT();
    int cur = 0;
    for (int kt = 0; kt < KT; kt++) {
        if (kt + 1 < KT) { load_AB(cur ^ 1, (kt + 1) * 32); CP_COMMIT(); CP_WAIT1(); }
        else CP_WAIT0();
        __syncthreads();
#pragma unroll
        for (int ks = 0; ks < 2; ks++) {
            int k0 = ks * 16;
            uint32_t af[4][4];
#pragma unroll
            for (int mi = 0; mi < 4; mi++) {
                uint32_t addr = smem_u32(&As[cur][wm * 64 + mi * 16 + (lane & 15)]
                                            [k0 + (lane >> 4) * 8]);
                asm volatile("ldmatrix.sync.aligned.m8n8.x4.shared.b16 {%0,%1,%2,%3}, [%4];"
                    : "=r"(af[mi][0]), "=r"(af[mi][1]), "=r"(af[mi][2]), "=r"(af[mi][3])
                    : "r"(addr));
            }
            uint32_t bfr[4][2];
#pragma unroll
            for (int ni = 0; ni < 4; ni++) {
                int l16 = lane & 15;
                uint32_t addr = smem_u32(&Bs[cur][wn * 32 + ni * 8 + (l16 & 7)]
                                            [k0 + (l16 >> 3) * 8]);
                asm volatile("ldmatrix.sync.aligned.m8n8.x2.shared.b16 {%0,%1}, [%2];"
                    : "=r"(bfr[ni][0]), "=r"(bfr[ni][1]) : "r"(addr));
            }
#pragma unroll
            for (int mi = 0; mi < 4; mi++)
#pragma unroll
                for (int ni = 0; ni < 4; ni++)
                    MMA16816H(acc[mi][ni], af[mi], bfr[ni]);
        }
        __syncthreads();
        cur ^= 1;
    }

#pragma unroll
    for (int mi = 0; mi < 4; mi++)
#pragma unroll
        for (int ni = 0; ni < 4; ni++) {
            int row = m0 + wm * 64 + mi * 16 + (lane >> 2);
            int col = n0 + wn * 32 + ni * 8 + (lane & 3) * 2;
            float2 v0 = {acc[mi][ni][0], acc[mi][ni][1]};
            float2 v1 = {acc[mi][ni][2], acc[mi][ni][3]};
            *(float2*)&C[(size_t)row * N + col]       = v0;
            *(float2*)&C[(size_t)(row + 8) * N + col] = v1;
        }
}

// ---------------- epilogue: xPos rotate -> Q2/K2 folded; k f32 back; v -> V2; silu gate ----------------
__global__ void k_epi() {
    int idx = blockIdx.x * blockDim.x + threadIdx.x;
    if (idx >= LSEQ * 1024) return;
    int l = idx >> 10, u = idx & 1023;
    int cch = l >> 7, t = l & 127;
    if (u < 512) {
        bool isK = (u >= 256);
        int p = u & 255;
        int n = p >> 5, j5 = p & 31;
        size_t pb = (size_t)l * PCOLS + (isK ? 512 : 0) + n * 64 + 2 * j5;
        float x1 = d_proj[pb], x2 = d_proj[pb + 1];
        float sc = isK ? d_sclK[l * 32 + j5] : d_sclQ[l * 32 + j5];
        float si = d_sinT[l * 32 + j5] * sc;
        float co = d_cosT[l * 32 + j5] * sc;
        float r1 = x1 * co - x2 * si;
        float r2 = x2 * co + x1 * si;
        bf16 h1 = __float2bfloat16(r1), h2 = __float2bfloat16(r2);
        bf16 l1 = __float2bfloat16(r1 - __bfloat162float(h1));
        bf16 l2 = __float2bfloat16(r2 - __bfloat162float(h2));
        size_t qb = ((size_t)(n * NC + cch) * 128 + t) * 192 + 2 * j5;
        if (!isK) {
            d_Q2[qb] = h1;       d_Q2[qb + 1] = h2;
            d_Q2[qb + 64] = l1;  d_Q2[qb + 65] = l2;
            d_Q2[qb + 128] = h1; d_Q2[qb + 129] = h2;
        } else {
            d_proj[pb] = r1; d_proj[pb + 1] = r2;   // f32 k for locstate
            d_K2[qb] = h1;       d_K2[qb + 1] = h2;
            d_K2[qb + 64] = h1;  d_K2[qb + 65] = h2;
            d_K2[qb + 128] = l1; d_K2[qb + 129] = l2;
        }
    } else {
        int vd = u - 512;
        int n = vd >> 6, j = vd & 63;
        float xv = d_proj[(size_t)l * PCOLS + 1024 + vd];
        bf16 vh = __float2bfloat16(xv);
        bf16 vl = __float2bfloat16(xv - __bfloat162float(vh));
        size_t vb = ((size_t)(n * NC + cch) * 64 + j) * 384 + t;  // V^T folded
        d_V2[vb] = vh; d_V2[vb + 128] = vh; d_V2[vb + 256] = vl;
        size_t gb = (size_t)l * PCOLS + 1536 + vd;
        float x = d_proj[gb];
        d_proj[gb] = x / (1.f + expf(-x));
    }
}

// ---------------- per-chunk local decay state (SIMT fp32) ----------------
__global__ void k_locstate() {
    int c = blockIdx.x, n = blockIdx.y;
    float g = gamma_of(n);
    __shared__ float sk[64][64];
    __shared__ float sv[64][64];
    __shared__ float wgt[CHUNK];
    int tid = threadIdx.x;
    if (tid < CHUNK) wgt[tid] = (float)pow((double)g, (double)(CHUNK - 1 - tid));
    __syncthreads();
    int tx = tid & 15, ty = tid >> 4;
    float acc[4][4];
#pragma unroll
    for (int i = 0; i < 4; i++)
#pragma unroll
        for (int j = 0; j < 4; j++) acc[i][j] = 0.f;

    for (int half = 0; half < 2; half++) {
#pragma unroll
        for (int i = 0; i < 16; i++) {
            int t4 = tid + i * 256;
            int rr = t4 >> 6, cc = t4 & 63;
            int s = c * CHUNK + half * 64 + rr;
            sk[rr][cc] = d_proj[(size_t)s * PCOLS + 512  + n * 64 + cc] * wgt[half * 64 + rr];
            sv[rr][cc] = d_proj[(size_t)s * PCOLS + 1024 + n * 64 + cc];
        }
        __syncthreads();
#pragma unroll
        for (int t = 0; t < 64; t++) {
            float4 a4 = *(const float4*)&sk[t][ty * 4];
            float4 b4 = *(const float4*)&sv[t][tx * 4];
            float a[4] = {a4.x, a4.y, a4.z, a4.w};
            float b[4] = {b4.x, b4.y, b4.z, b4.w};
#pragma unroll
            for (int i = 0; i < 4; i++)
#pragma unroll
                for (int j = 0; j < 4; j++) acc[i][j] += a[i] * b[j];
        }
        __syncthreads();
    }
#pragma unroll
    for (int i = 0; i < 4; i++)
#pragma unroll
        for (int j = 0; j < 4; j++)
            d_Sloc[(size_t)((n * NC + c) * 64 + ty * 4 + i) * 64 + tx * 4 + j] = acc[i][j];
}

// ---------------- parallel scan -> S2 folded ----------------
__global__ void k_scan2() {
    int idx = blockIdx.x * blockDim.x + threadIdx.x;   // 32768
    int n = idx >> 12, e = idx & 4095;
    int i = e >> 6, j = e & 63;
    float g = gamma_of(n);
    float g128 = (float)pow((double)g, 128.0);
    float s = 0.f;
#pragma unroll 1
    for (int c = 0; c < NC; c++) {
        bf16 sh = __float2bfloat16(s);
        bf16 sl = __float2bfloat16(s - __bfloat162float(sh));
        size_t sb = ((size_t)(n * NC + c) * 64 + j) * 192 + i;
        d_S2[sb] = sh; d_S2[sb + 64] = sh; d_S2[sb + 128] = sl;
        s = g128 * s + d_Sloc[(size_t)(n * NC + c) * 4096 + e];
    }
}

// ---------------- phase A: P = (Q K^T) ⊙ decay, per (n,c), HMMA, emit folded P2 ----------------
__global__ void __launch_bounds__(256) k_pa() {
    __shared__ bf16 As[2][128][40];
    __shared__ bf16 Bs[2][128][40];
    __shared__ float gpow[CHUNK];
    int c = blockIdx.x, n = blockIdx.y;
    int tid = threadIdx.x, lane = tid & 31, wid = tid >> 5;
    int wm = wid & 1, wn = wid >> 1;
    float g = gamma_of(n);
    if (tid < CHUNK) gpow[tid] = (float)pow((double)g, (double)tid);

    const bf16* A = d_Q2 + (size_t)(n * NC + c) * 128 * 192;
    const bf16* B = d_K2 + (size_t)(n * NC + c) * 128 * 192;

    float acc[4][4][4];
#pragma unroll
    for (int i = 0; i < 4; i++)
#pragma unroll
        for (int j = 0; j < 4; j++)
#pragma unroll
            for (int r2 = 0; r2 < 4; r2++) acc[i][j][r2] = 0.f;

    auto load_AB = [&](int buf, int k0) {
#pragma unroll
        for (int i = 0; i < 2; i++) {
            int ch = tid + i * 256;
            int row = ch >> 2, c16 = ch & 3;
            CP_ASYNC16(smem_u32(&As[buf][row][c16 * 8]), A + (size_t)row * 192 + k0 + c16 * 8);
            CP_ASYNC16(smem_u32(&Bs[buf][row][c16 * 8]), B + (size_t)row * 192 + k0 + c16 * 8);
        }
    };

    const int KT = 6;
    load_AB(0, 0);
    CP_COMMIT();
    int cur = 0;
    for (int kt = 0; kt < KT; kt++) {
        if (kt + 1 < KT) { load_AB(cur ^ 1, (kt + 1) * 32); CP_COMMIT(); CP_WAIT1(); }
        else CP_WAIT0();
        __syncthreads();
#pragma unroll
        for (int ks = 0; ks < 2; ks++) {
            int k0 = ks * 16;
            uint32_t af[4][4];
#pragma unroll
            for (int mi = 0; mi < 4; mi++) {
                uint32_t addr = smem_u32(&As[cur][wm * 64 + mi * 16 + (lane & 15)]
                                            [k0 + (lane >> 4) * 8]);
                asm volatile("ldmatrix.sync.aligned.m8n8.x4.shared.b16 {%0,%1,%2,%3}, [%4];"
                    : "=r"(af[mi][0]), "=r"(af[mi][1]), "=r"(af[mi][2]), "=r"(af[mi][3])
                    : "r"(addr));
            }
            uint32_t bfr[4][2];
#pragma unroll
            for (int ni = 0; ni < 4; ni++) {
                int l16 = lane & 15;
                uint32_t addr = smem_u32(&Bs[cur][wn * 32 + ni * 8 + (l16 & 7)]
                                            [k0 + (l16 >> 3) * 8]);
                asm volatile("ldmatrix.sync.aligned.m8n8.x2.shared.b16 {%0,%1}, [%2];"
                    : "=r"(bfr[ni][0]), "=r"(bfr[ni][1]) : "r"(addr));
            }
#pragma unroll
            for (int mi = 0; mi < 4; mi++)
#pragma unroll
                for (int ni = 0; ni < 4; ni++)
                    MMA16816(acc[mi][ni], af[mi], bfr[ni]);
        }
        __syncthreads();
        cur ^= 1;
    }

    size_t pbase = (size_t)(n * NC + c) * 128 * 384;
#pragma unroll
    for (int mi = 0; mi < 4; mi++)
#pragma unroll
        for (int ni = 0; ni < 4; ni++) {
            int s0 = wn * 32 + ni * 8 + (lane & 3) * 2;
#pragma unroll
            for (int h = 0; h < 2; h++) {
                int t = wm * 64 + mi * 16 + (lane >> 2) + h * 8;
                float p0 = acc[mi][ni][h * 2], p1 = acc[mi][ni][h * 2 + 1];
                p0 = (s0 <= t)     ? p0 * gpow[t - s0]     : 0.f;
                p1 = (s0 + 1 <= t) ? p1 * gpow[t - s0 - 1] : 0.f;
                bf16 h0 = __float2bfloat16(p0), h1b = __float2bfloat16(p1);
                __nv_bfloat162 hh; hh.x = h0; hh.y = h1b;
                __nv_bfloat162 ll;
                ll.x = __float2bfloat16(p0 - __bfloat162float(h0));
                ll.y = __float2bfloat16(p1 - __bfloat162float(h1b));
                size_t base = pbase + (size_t)t * 384 + s0;
                *(__nv_bfloat162*)&d_P2[base]       = hh;
                *(__nv_bfloat162*)&d_P2[base + 128] = ll;
                *(__nv_bfloat162*)&d_P2[base + 256] = hh;
            }
        }
}

// ---------------- phase B: out = P@V + g^(t+1) * Q@S_in, per (n,c), HMMA ----------------
__global__ void __launch_bounds__(256) k_pb() {
    __shared__ bf16 As[2][128][40];
    __shared__ bf16 Bs[2][64][40];
    __shared__ float gpow[CHUNK + 1];
    int c = blockIdx.x, n = blockIdx.y;
    int tid = threadIdx.x, lane = tid & 31, wid = tid >> 5;
    int wm = wid & 3, wn = wid >> 2;
    float g = gamma_of(n);
    if (tid <= CHUNK) gpow[tid] = (float)pow((double)g, (double)tid);

    float acc1[2][4][4], acc2[2][4][4];
#pragma unroll
    for (int i = 0; i < 2; i++)
#pragma unroll
        for (int j = 0; j < 4; j++)
#pragma unroll
            for (int r2 = 0; r2 < 4; r2++) { acc1[i][j][r2] = 0.f; acc2[i][j][r2] = 0.f; }

    auto run_pass = [&](const bf16* A, const bf16* B, int Ktot, float (*acc)[4][4]) {
        auto load_AB = [&](int buf, int k0) {
#pragma unroll
            for (int i = 0; i < 2; i++) {
                int ch = tid + i * 256;
                int row = ch >> 2, c16 = ch & 3;
                CP_ASYNC16(smem_u32(&As[buf][row][c16 * 8]), A + (size_t)row * Ktot + k0 + c16 * 8);
            }
            int row = tid >> 2, c16 = tid & 3;
            CP_ASYNC16(smem_u32(&Bs[buf][row][c16 * 8]), B + (size_t)row * Ktot + k0 + c16 * 8);
        };
        int KT = Ktot / 32;
        load_AB(0, 0);
        CP_COMMIT();
        int cur = 0;
        for (int kt = 0; kt < KT; kt++) {
            if (kt + 1 < KT) { load_AB(cur ^ 1, (kt + 1) * 32); CP_COMMIT(); CP_WAIT1(); }
            else CP_WAIT0();
            __syncthreads();
#pragma unroll
            for (int ks = 0; ks < 2; ks++) {
                int k0 = ks * 16;
                uint32_t af[2][4];
#pragma unroll
                for (int mi = 0; mi < 2; mi++) {
                    uint32_t addr = smem_u32(&As[cur][wm * 32 + mi * 16 + (lane & 15)]
                                                [k0 + (lane >> 4) * 8]);
                    asm volatile("ldmatrix.sync.aligned.m8n8.x4.shared.b16 {%0,%1,%2,%3}, [%4];"
                        : "=r"(af[mi][0]), "=r"(af[mi][1]), "=r"(af[mi][2]), "=r"(af[mi][3])
                        : "r"(addr));
                }
                uint32_t bfr[4][2];
#pragma unroll
                for (int ni = 0; ni < 4; ni++) {
                    int l16 = lane & 15;
                    uint32_t addr = smem_u32(&Bs[cur][wn * 32 + ni * 8 + (l16 & 7)]
                                                [k0 + (l16 >> 3) * 8]);
                    asm volatile("ldmatrix.sync.aligned.m8n8.x2.shared.b16 {%0,%1}, [%2];"
                        : "=r"(bfr[ni][0]), "=r"(bfr[ni][1]) : "r"(addr));
                }
#pragma unroll
                for (int mi = 0; mi < 2; mi++)
#pragma unroll
                    for (int ni = 0; ni < 4; ni++)
                        MMA16816(acc[mi][ni], af[mi], bfr[ni]);
            }
            __syncthreads();
            cur ^= 1;
        }
    };

    run_pass(d_P2 + (size_t)(n * NC + c) * 128 * 384,
             d_V2 + (size_t)(n * NC + c) * 64 * 384, 384, acc1);
    run_pass(d_Q2 + (size_t)(n * NC + c) * 128 * 192,
             d_S2 + (size_t)(n * NC + c) * 64 * 192, 192, acc2);

#pragma unroll
    for (int mi = 0; mi < 2; mi++)
#pragma unroll
        for (int ni = 0; ni < 4; ni++) {
            int j = wn * 32 + ni * 8 + (lane & 3) * 2;
#pragma unroll
            for (int h = 0; h < 2; h++) {
                int t = wm * 32 + mi * 16 + (lane >> 2) + h * 8;
                float dec = gpow[t + 1];
                float2 o;
                o.x = acc1[mi][ni][h * 2]     + dec * acc2[mi][ni][h * 2];
                o.y = acc1[mi][ni][h * 2 + 1] + dec * acc2[mi][ni][h * 2 + 1];
                *(float2*)&d_ret[(size_t)(n * LSEQ + c * CHUNK + t) * 64 + j] = o;
            }
        }
}

// ---------------- groupnorm * gate -> fp16 [gh | gl] rows of d_g2 ----------------
__global__ void k_gnorm(const float* __restrict__ gnw, const float* __restrict__ gnb) {
    int warp = threadIdx.x >> 5, lane = threadIdx.x & 31;
    int grp = blockIdx.x * 8 + warp;
    int l = grp >> 3, n = grp & 7;
    const float* rp = &d_ret[(size_t)(n * LSEQ + l) * 64];
    float v0 = rp[lane], v1 = rp[lane + 32];
    float s = v0 + v1, ss = v0 * v0 + v1 * v1;
#pragma unroll
    for (int off = 16; off; off >>= 1) {
        s  += __shfl_xor_sync(0xffffffffu, s,  off);
        ss += __shfl_xor_sync(0xffffffffu, ss, off);
    }
    float mean = s * (1.f / 64.f);
    float var  = ss * (1.f / 64.f) - mean * mean;
    float inv  = rsqrtf(var + 1e-5f);
    int col = n * 64 + lane;
    float g0 = (v0 - mean) * inv * gnw[col]      + gnb[col];
    float g1 = (v1 - mean) * inv * gnw[col + 32] + gnb[col + 32];
    float gate0 = d_proj[(size_t)l * PCOLS + 1536 + col];
    float gate1 = d_proj[(size_t)l * PCOLS + 1536 + col + 32];
    float o0 = gate0 * g0, o1 = gate1 * g1;
    size_t b = (size_t)l * KG;
    fp16 h0 = __float2half(o0);
    fp16 h1 = __float2half(o1);
    d_g2[b + col]            = h0;
    d_g2[b + 512 + col]      = __float2half(o0 - __half2float(h0));
    d_g2[b + col + 32]       = h1;
    d_g2[b + 512 + col + 32] = __float2half(o1 - __half2float(h1));
}

// ---------------- launch ----------------
extern "C" void kernel_launch(void* const* d_in, const int* in_sizes, int n_in,
                              void* d_out, int out_size) {
    (void)in_sizes; (void)n_in; (void)out_size;
    const float* X   = (const float*)d_in[0];
    const float* WQ  = (const float*)d_in[1];
    const float* WK  = (const float*)d_in[2];
    const float* WV  = (const float*)d_in[3];
    const float* WG  = (const float*)d_in[4];
    const float* WO  = (const float*)d_in[5];
    const float* gnw = (const float*)d_in[6];
    const float* gnb = (const float*)d_in[7];
    float* out = (float*)d_out;

    void *pProj = nullptr, *pA2 = nullptr, *pB2 = nullptr, *pWO2 = nullptr, *pG2 = nullptr;
    cudaGetSymbolAddress(&pProj, d_proj);
    cudaGetSymbolAddress(&pA2,  d_A2);
    cudaGetSymbolAddress(&pB2,  d_B2);
    cudaGetSymbolAddress(&pWO2, d_WO2);
    cudaGetSymbolAddress(&pG2,  d_g2);

    k_tables<<<(LSEQ * HALF + 255) / 256, 256>>>();
    k_convA<<<(LSEQ * DIM + 255) / 256, 256>>>(X);
    k_packB<<<(PCOLS * DIM + 255) / 256, 256>>>(WQ, WK, WV, WG);
    k_packWO<<<(DIM * DIM + 255) / 256, 256>>>(WO);
    k_mma<<<dim3(PCOLS / 128, LSEQ / 128), 256>>>(
        (const fp16*)pA2, (const fp16*)pB2, (float*)pProj, PCOLS);
    k_epi<<<(LSEQ * 1024 + 255) / 256, 256>>>();
    k_locstate<<<dim3(NC, NH), 256>>>();
    k_scan2<<<128, 256>>>();
    k_pa<<<dim3(NC, NH), 256>>>();
    k_pb<<<dim3(NC, NH), 256>>>();
    k_gnorm<<<LSEQ, 256>>>(gnw, gnb);
    k_mma<<<dim3(DIM / 128, LSEQ / 128), 256>>>(
        (const fp16*)pG2, (const fp16*)pWO2, out, DIM);
}